// round 7
// baseline (speedup 1.0000x reference)
#include <cuda_runtime.h>

// ============================================================================
// AdderNet TauNet R7: warp-pair per quad (64-lane coop), FFMA-imm diffs.
// ============================================================================

#define EPSV 1e-5f

// ---- s_small layout (floats) ----
#define W1OFF  0
#define W2OFF  80
#define R1OFF  680
#define R2OFF  800
#define A1OFF  920
#define B1OFF  925
#define A2OFF  930
#define B2OFF  940
#define AR1OFF 950
#define BR1OFF 960
#define AR2OFF 970
#define BR2OFF 980
#define AOAOFF 990
#define BOAOFF 1130
#define AOBOFF 1270
#define BOBOFF 1330
#define AOCOFF 1390
#define BOCOFF 1392
#define QOCOFF 1400
#define SMALL_N 1464

__device__ float g_small[1472];
__device__ float g_qoa[2 * 35 * 70 * 4];   // [branch][i/4][c][4]
__device__ float g_qob[2 * 18 * 30 * 4];

__device__ __forceinline__ float quantv(float w, float s) {
    float t = fminf(fmaxf(w / s, -127.f), 127.f);
    return rintf(t) * s;
}

__device__ __forceinline__ void fill_bn(const float* bn, int c, float* A, float* Bt) {
    for (int i = threadIdx.x; i < c; i += blockDim.x) {
        float g = bn[i], b = bn[c + i], m = bn[2 * c + i], v = bn[3 * c + i];
        float al = g * rsqrtf(v + EPSV);
        A[i] = al;
        Bt[i] = b - m * al;
    }
}

// ---------------------------------------------------------------------------
__global__ void setup_kernel(
    const float* __restrict__ w1,   const float* __restrict__ w2,
    const float* __restrict__ wr1,  const float* __restrict__ wr2,
    const float* __restrict__ wo1a, const float* __restrict__ wo1b, const float* __restrict__ wo1c,
    const float* __restrict__ wo2a, const float* __restrict__ wo2b, const float* __restrict__ wo2c,
    const float* __restrict__ bn1,  const float* __restrict__ bn2,
    const float* __restrict__ bnr1, const float* __restrict__ bnr2,
    const float* __restrict__ bno1a, const float* __restrict__ bno1b, const float* __restrict__ bno1c,
    const float* __restrict__ bno2a, const float* __restrict__ bno2b, const float* __restrict__ bno2c)
{
    const int blk = blockIdx.x, tid = threadIdx.x;
    if (blk < 10) {
        const float* w; int n;
        switch (blk) {
            case 0: w = w1;   n = 65;   break;
            case 1: w = w2;   n = 450;  break;
            case 2: w = wr1;  n = 100;  break;
            case 3: w = wr2;  n = 100;  break;
            case 4: w = wo1a; n = 9800; break;
            case 5: w = wo2a; n = 9800; break;
            case 6: w = wo1b; n = 2100; break;
            case 7: w = wo2b; n = 2100; break;
            case 8: w = wo1c; n = 30;   break;
            default: w = wo2c; n = 30;  break;
        }
        __shared__ float red[256];
        float m = 0.f;
        for (int i = tid; i < n; i += 256) m = fmaxf(m, fabsf(w[i]));
        red[tid] = m;
        __syncthreads();
        for (int s = 128; s > 0; s >>= 1) {
            if (tid < s) red[tid] = fmaxf(red[tid], red[tid + s]);
            __syncthreads();
        }
        const float s = red[0] / 127.f;

        if (blk == 0) {
            for (int j = tid; j < 80; j += 256) {
                int c = j >> 4, k = j & 15;
                g_small[W1OFF + j] = (k < 13) ? quantv(w[c * 13 + k], s) : 0.f;
            }
        } else if (blk == 1) {
            for (int j = tid; j < 600; j += 256) {
                int row = j / 12, k = j - row * 12;
                g_small[W2OFF + j] = (k < 9) ? quantv(w[row * 9 + k], s) : 0.f;
            }
        } else if (blk == 2 || blk == 3) {
            float* dst = g_small + (blk == 2 ? R1OFF : R2OFF);
            for (int j = tid; j < 120; j += 256) {
                int c = j / 12, k = j - c * 12;
                dst[j] = (k < 10) ? quantv(w[c * 10 + k], s) : 0.f;
            }
        } else if (blk == 4 || blk == 5) {
            float* dst = g_qoa + (blk - 4) * 9800;
            for (int j = tid; j < 9800; j += 256) {
                int i4 = j / 280, rem = j - i4 * 280;
                int c = rem >> 2, t = rem & 3;
                dst[j] = quantv(w[c * 140 + i4 * 4 + t], s);
            }
        } else if (blk == 6 || blk == 7) {
            float* dst = g_qob + (blk - 6) * 2160;
            for (int j = tid; j < 2160; j += 256) {
                int i4 = j / 120, rem = j - i4 * 120;
                int c = rem >> 2, t = rem & 3;
                int i = i4 * 4 + t;
                dst[j] = (i < 70) ? quantv(w[c * 70 + i], s) : 0.f;
            }
        } else {
            float* dst = g_small + QOCOFF + (blk - 8) * 32;
            if (tid < 32) dst[tid] = (tid < 30) ? quantv(w[tid], s) : 0.f;
        }
    } else {
        fill_bn(bn1, 5,  g_small + A1OFF,  g_small + B1OFF);
        fill_bn(bn2, 10, g_small + A2OFF,  g_small + B2OFF);
        fill_bn(bnr1, 10, g_small + AR1OFF, g_small + BR1OFF);
        fill_bn(bnr2, 10, g_small + AR2OFF, g_small + BR2OFF);
        fill_bn(bno1a, 70, g_small + AOAOFF,      g_small + BOAOFF);
        fill_bn(bno2a, 70, g_small + AOAOFF + 70, g_small + BOAOFF + 70);
        fill_bn(bno1b, 30, g_small + AOBOFF,      g_small + BOBOFF);
        fill_bn(bno2b, 30, g_small + AOBOFF + 30, g_small + BOBOFF + 30);
        fill_bn(bno1c, 1, g_small + AOCOFF,     g_small + BOCOFF);
        fill_bn(bno2c, 1, g_small + AOCOFF + 1, g_small + BOCOFF + 1);
    }
}

// ---------------------------------------------------------------------------
// Per-QUAD workspace (floats), two quads per CTA (warp-pair each).
//   X  @0     float4[256] (1024)   [T aliases X; A aliases X]
//   H1 @1024  float4[245] (980)    stride-49 rows  [F aliases H1]
//   H2 @2004  float4[144] (576)    [B aliases H2]
#define XOFF  0
#define H1OFF 1024
#define H2OFF 2004
#define FOFF  1024
#define AOFF  0
#define BOFF  2004
#define WS_N  2580

__device__ __forceinline__ void ld4(float* d, const float* s) {
    float4 v = *(const float4*)s;
    d[0] = v.x; d[1] = v.y; d[2] = v.z; d[3] = v.w;
}

// acc[e] += |u[e] - w|  ; diff via FFMA-imm (rt 1) instead of FADD (rt 2)
__device__ __forceinline__ void acc4(float4& a, float4 u, float w) {
    a.x += fabsf(fmaf(w, -1.0f, u.x));
    a.y += fabsf(fmaf(w, -1.0f, u.y));
    a.z += fabsf(fmaf(w, -1.0f, u.z));
    a.w += fabsf(fmaf(w, -1.0f, u.w));
}

__device__ __forceinline__ float4 add4(float4 a, float4 b) {
    return make_float4(a.x + b.x, a.y + b.y, a.z + b.z, a.w + b.w);
}

__device__ __forceinline__ float4 bnrelu4(float4 a, float al, float be) {
    return make_float4(fmaxf(fmaf(-a.x, al, be), 0.f),
                       fmaxf(fmaf(-a.y, al, be), 0.f),
                       fmaxf(fmaf(-a.z, al, be), 0.f),
                       fmaxf(fmaf(-a.w, al, be), 0.f));
}

#define ZERO4 make_float4(0.f, 0.f, 0.f, 0.f)

__global__ void __launch_bounds__(128) taunet_main(const float* __restrict__ x,
                                                   float* __restrict__ out, int nB)
{
    __shared__ __align__(16) float s_small[SMALL_N];
    __shared__ __align__(16) float s_ws[2][WS_N];

    for (int i = threadIdx.x; i < SMALL_N; i += 128) s_small[i] = g_small[i];

    const int tid  = threadIdx.x;
    const int half = tid >> 6;          // which quad of the CTA
    const int t64  = tid & 63;          // lane within the 64-thread group
    const int wp   = (tid >> 5) & 1;    // warp within the pair
    const int lane = tid & 31;

    float* ws = s_ws[half];
    float4* X4  = (float4*)(ws + XOFF);
    float4* H14 = (float4*)(ws + H1OFF);
    float4* H24 = (float4*)(ws + H2OFF);
    float4* T4  = (float4*)(ws + XOFF);
    float4* F4  = (float4*)(ws + FOFF);
    float4* A4  = (float4*)(ws + AOFF);
    float4* B4  = (float4*)(ws + BOFF);

    // ---- oa slot mapping for 64 lanes (channels t64, t64+64, t64+128) ----
    const int j1 = t64 + 64;
    const int qa1 = (j1 < 70) ? j1 : (2450 + (j1 - 70));
    const int da1 = (j1 < 70) ? j1 : (72 + (j1 - 70));
    const int j2 = t64 + 128;                 // valid if t64 < 12
    const int qa2 = 2450 + (j2 - 70);
    const int da2 = 72 + (j2 - 70);
    const bool s2 = (t64 < 12);
    // ob: channel t64 (< 60)
    const int obb = (t64 < 60) ? (t64 / 30) : 1;
    const int obc = (t64 < 60) ? (t64 - 30 * obb) : 29;
    const int qb  = obb * 540 + obc;
    const int db  = obb * 32 + obc;

    const int nQ = (nB + 3) >> 2;
    const int nQB = (nQ + 1) >> 1;     // quad-pairs per sweep

    __syncthreads();

    for (int qb2 = blockIdx.x; qb2 < nQB; qb2 += gridDim.x) {
        const int qr = 2 * qb2 + half;
        const bool qok = (qr < nQ);
        const int q = qok ? qr : (nQ - 1);
        const int e0 = 4 * q;
        const int e1 = (e0 + 1 < nB) ? e0 + 1 : nB - 1;
        const int e2 = (e0 + 2 < nB) ? e0 + 2 : nB - 1;
        const int e3 = (e0 + 3 < nB) ? e0 + 3 : nB - 1;

        // ---- stage 4 input rows, transposed (each lane: one float4 column) --
        {
            const float4* r0 = (const float4*)(x + (size_t)e0 * 256);
            const float4* r1 = (const float4*)(x + (size_t)e1 * 256);
            const float4* r2 = (const float4*)(x + (size_t)e2 * 256);
            const float4* r3 = (const float4*)(x + (size_t)e3 * 256);
            float4 a = __ldg(r0 + t64);
            float4 b = __ldg(r1 + t64);
            float4 c = __ldg(r2 + t64);
            float4 d = __ldg(r3 + t64);
            X4[4 * t64 + 0] = make_float4(a.x, b.x, c.x, d.x);
            X4[4 * t64 + 1] = make_float4(a.y, b.y, c.y, d.y);
            X4[4 * t64 + 2] = make_float4(a.z, b.z, c.z, d.z);
            X4[4 * t64 + 3] = make_float4(a.w, b.w, c.w, d.w);
        }
        __syncthreads();

        // ---- pre1: 125 dual-position tasks (5ch x 25pd), K=13, stride 5 ----
        #pragma unroll 1
        for (int r = 0; r < 2; r++) {
            int idx = t64 + 64 * r;
            if (idx < 125) {
                int c = idx / 25, pd = idx - 25 * c;
                int p0 = 2 * pd;
                bool dual = (pd < 24);
                float w[16];
                const float* wb = s_small + W1OFF + c * 16;
                ld4(w, wb); ld4(w + 4, wb + 4); ld4(w + 8, wb + 8); ld4(w + 12, wb + 12);
                const float4* xp = X4 + 5 * p0;
                float4 A0 = ZERO4, B0 = ZERO4, A1 = ZERO4, B1 = ZERO4;
                #pragma unroll
                for (int k = 0; k < 13; k++) {
                    float4 a = xp[k];
                    if (k & 1) acc4(B0, a, w[k]); else acc4(A0, a, w[k]);
                    if (k >= 5) {
                        if ((k - 5) & 1) acc4(B1, a, w[k - 5]); else acc4(A1, a, w[k - 5]);
                    }
                }
                if (dual) {
                    #pragma unroll
                    for (int k = 13; k < 18; k++) {
                        float4 a = xp[k];
                        if ((k - 5) & 1) acc4(B1, a, w[k - 5]); else acc4(A1, a, w[k - 5]);
                    }
                }
                float al = s_small[A1OFF + c], be = s_small[B1OFF + c];
                H14[c * 49 + p0] = bnrelu4(add4(A0, B0), al, be);
                if (dual)
                    H14[c * 49 + p0 + 1] = bnrelu4(add4(A1, B1), al, be);
            }
        }
        __syncthreads();

        // ---- pre2: 140 tasks (10ch x 14pos), 5cin x K=9, stride 3 ----
        #pragma unroll 1
        for (int r = 0; r < 3; r++) {
            int idx = t64 + 64 * r;
            if (idx < 140) {
                int c = idx / 14, p = idx - 14 * c;
                const float4* hp = H14 + 3 * p;
                float4 Aa = ZERO4, Bb = ZERO4;
                #pragma unroll
                for (int ci = 0; ci < 5; ci++) {
                    float w[12];
                    const float* wb = s_small + W2OFF + (c * 5 + ci) * 12;
                    ld4(w, wb); ld4(w + 4, wb + 4); ld4(w + 8, wb + 8);
                    const float4* hc = hp + ci * 49;
                    #pragma unroll
                    for (int k = 0; k < 9; k++) {
                        if (k & 1) acc4(Bb, hc[k], w[k]); else acc4(Aa, hc[k], w[k]);
                    }
                }
                H24[c * 14 + p] = bnrelu4(add4(Aa, Bb), s_small[A2OFF + c], s_small[B2OFF + c]);
            }
        }
        __syncthreads();

        // ---- r1: 140 tasks, 10 taps (T over dead X) ----
        #pragma unroll 1
        for (int r = 0; r < 3; r++) {
            int idx = t64 + 64 * r;
            if (idx < 140) {
                int c = idx / 14, p = idx - 14 * c;
                float w[12];
                const float* wb = s_small + R1OFF + c * 12;
                ld4(w, wb); ld4(w + 4, wb + 4); ld4(w + 8, wb + 8);
                float4 a = ZERO4;
                #pragma unroll
                for (int ci = 0; ci < 10; ci++) acc4(a, H24[ci * 14 + p], w[ci]);
                T4[c * 14 + p] = bnrelu4(a, s_small[AR1OFF + c], s_small[BR1OFF + c]);
            }
        }
        __syncthreads();

        // ---- r2 + residual (F over dead H1) ----
        #pragma unroll 1
        for (int r = 0; r < 3; r++) {
            int idx = t64 + 64 * r;
            if (idx < 140) {
                int c = idx / 14, p = idx - 14 * c;
                float w[12];
                const float* wb = s_small + R2OFF + c * 12;
                ld4(w, wb); ld4(w + 4, wb + 4); ld4(w + 8, wb + 8);
                float4 a = ZERO4;
                #pragma unroll
                for (int ci = 0; ci < 10; ci++) acc4(a, T4[ci * 14 + p], w[ci]);
                float al = s_small[AR2OFF + c], be = s_small[BR2OFF + c];
                float4 h2v = H24[c * 14 + p];
                F4[c * 14 + p] = make_float4(
                    fmaxf(fmaf(-a.x, al, be) + h2v.x, 0.f),
                    fmaxf(fmaf(-a.y, al, be) + h2v.y, 0.f),
                    fmaxf(fmaf(-a.z, al, be) + h2v.z, 0.f),
                    fmaxf(fmaf(-a.w, al, be) + h2v.w, 0.f));
            }
        }
        if (t64 < 4) F4[140 + t64] = ZERO4;
        __syncthreads();

        // ---- oa: 3 channel slots x 4 packed elements over 64 lanes ----
        {
            float4 a0 = ZERO4, a1 = ZERO4, a2 = ZERO4;
            const float4* QA = (const float4*)g_qoa;

            #pragma unroll 5
            for (int i4 = 0; i4 < 35; i4++) {
                float4 u0 = F4[4 * i4 + 0];
                float4 u1 = F4[4 * i4 + 1];
                float4 u2 = F4[4 * i4 + 2];
                float4 u3 = F4[4 * i4 + 3];
                const float4* qrow = QA + i4 * 70;
                float4 w = __ldg(qrow + t64);
                acc4(a0, u0, w.x); acc4(a0, u1, w.y); acc4(a0, u2, w.z); acc4(a0, u3, w.w);
                w = __ldg(qrow + qa1);
                acc4(a1, u0, w.x); acc4(a1, u1, w.y); acc4(a1, u2, w.z); acc4(a1, u3, w.w);
                if (s2) {
                    w = __ldg(qrow + qa2);
                    acc4(a2, u0, w.x); acc4(a2, u1, w.y); acc4(a2, u2, w.z); acc4(a2, u3, w.w);
                }
            }
            // A overwrites X/T region (disjoint from F) — no sync needed here.
            A4[t64] = bnrelu4(a0, s_small[AOAOFF + t64], s_small[BOAOFF + t64]);
            A4[da1] = bnrelu4(a1, s_small[AOAOFF + j1], s_small[BOAOFF + j1]);
            if (s2)
                A4[da2] = bnrelu4(a2, s_small[AOAOFF + j2], s_small[BOAOFF + j2]);
            if (t64 < 2) {
                A4[70 + t64]  = ZERO4;
                A4[142 + t64] = ZERO4;
            }
        }
        __syncthreads();

        // ---- ob: 60 channels over lanes 0..59 ----
        {
            float4 b = ZERO4;
            if (t64 < 60) {
                const float4* QB = (const float4*)g_qob;
                const float4* ap = A4 + obb * 72;
                #pragma unroll 6
                for (int i4 = 0; i4 < 18; i4++) {
                    float4 w = __ldg(QB + i4 * 30 + qb);
                    acc4(b, ap[4 * i4 + 0], w.x);
                    acc4(b, ap[4 * i4 + 1], w.y);
                    acc4(b, ap[4 * i4 + 2], w.z);
                    acc4(b, ap[4 * i4 + 3], w.w);
                }
            }
            __syncthreads();   // A reads done; B overwrites H2 region
            if (t64 < 60)
                B4[db] = bnrelu4(b, s_small[AOBOFF + t64], s_small[BOBOFF + t64]);
            if (t64 < 2) {
                B4[30 + t64] = ZERO4;
                B4[62 + t64] = ZERO4;
            }
        }
        __syncthreads();

        // ---- oc: warp wp handles branch wp (4 elems) ----
        {
            float wv = s_small[QOCOFF + wp * 32 + lane];
            float4 pv = B4[wp * 32 + lane];
            float v0 = fabsf(pv.x - wv);
            float v1 = fabsf(pv.y - wv);
            float v2 = fabsf(pv.z - wv);
            float v3 = fabsf(pv.w - wv);
            #pragma unroll
            for (int s = 16; s > 0; s >>= 1) {
                v0 += __shfl_xor_sync(0xffffffffu, v0, s);
                v1 += __shfl_xor_sync(0xffffffffu, v1, s);
                v2 += __shfl_xor_sync(0xffffffffu, v2, s);
                v3 += __shfl_xor_sync(0xffffffffu, v3, s);
            }
            if (lane == 0 && qok) {
                float al = s_small[AOCOFF + wp], be = s_small[BOCOFF + wp];
                float* o = out + (size_t)wp * nB;
                float v[4] = {v0, v1, v2, v3};
                #pragma unroll
                for (int i = 0; i < 4; i++)
                    if (e0 + i < nB) o[e0 + i] = fmaxf(fmaf(-v[i], al, be), 0.f);
            }
        }
        __syncthreads();   // B reads done before next iteration overwrites
    }
}

// ---------------------------------------------------------------------------
extern "C" void kernel_launch(void* const* d_in, const int* in_sizes, int n_in,
                              void* d_out, int out_size)
{
    const float* x     = (const float*)d_in[0];
    const float* w1    = (const float*)d_in[1];
    const float* bn1   = (const float*)d_in[2];
    const float* w2    = (const float*)d_in[3];
    const float* bn2   = (const float*)d_in[4];
    const float* wr1   = (const float*)d_in[5];
    const float* bnr1  = (const float*)d_in[6];
    const float* wr2   = (const float*)d_in[7];
    const float* bnr2  = (const float*)d_in[8];
    const float* wo1a  = (const float*)d_in[9];
    const float* bno1a = (const float*)d_in[10];
    const float* wo1b  = (const float*)d_in[11];
    const float* bno1b = (const float*)d_in[12];
    const float* wo1c  = (const float*)d_in[13];
    const float* bno1c = (const float*)d_in[14];
    const float* wo2a  = (const float*)d_in[15];
    const float* bno2a = (const float*)d_in[16];
    const float* wo2b  = (const float*)d_in[17];
    const float* bno2b = (const float*)d_in[18];
    const float* wo2c  = (const float*)d_in[19];
    const float* bno2c = (const float*)d_in[20];

    const int nB = in_sizes[0] / 256;
    const int nQ = (nB + 3) >> 2;
    const int nQB = (nQ + 1) >> 1;
    const int grid = (nQB < 1024) ? nQB : 1024;

    setup_kernel<<<11, 256>>>(w1, w2, wr1, wr2, wo1a, wo1b, wo1c, wo2a, wo2b, wo2c,
                              bn1, bn2, bnr1, bnr2, bno1a, bno1b, bno1c,
                              bno2a, bno2b, bno2c);
    taunet_main<<<grid, 128>>>(x, (float*)d_out, nB);
}

// round 8
// speedup vs baseline: 1.1197x; 1.1197x over previous
#include <cuda_runtime.h>

// ============================================================================
// AdderNet TauNet R8: R6 (warp-per-quad, dual-pos pre1, pos-major r1/r2)
//                     + FFMA-imm diffs (rt 1 vs FADD rt 2).
// ============================================================================

#define EPSV 1e-5f

// ---- s_small layout (floats), compact ----
#define W1OFF   0      // 5 x 16
#define W2OFF   80     // 50 x 12
#define R1TOFF  680    // 10ci x 16  (transposed: [ci][8g + j] = w[5g+j][ci])
#define R2TOFF  840    // 10ci x 16
#define A1OFF   1000
#define B1OFF   1005
#define A2OFF   1010
#define B2OFF   1020
#define AR1OFF  1030
#define BR1OFF  1040
#define AR2OFF  1050
#define BR2OFF  1060
#define AOAOFF  1070   // 140
#define BOAOFF  1210   // 140
#define AOBOFF  1350   // 60
#define BOBOFF  1410   // 60
#define AOCOFF  1470   // 2
#define BOCOFF  1472   // 2
#define QOCOFF  1474   // 64
#define SMALL_N 1540

__device__ float g_small[1544];
__device__ float g_qoa[2 * 35 * 70 * 4];   // [branch][i/4][c][4]
__device__ float g_qob[2 * 18 * 30 * 4];

__device__ __forceinline__ float quantv(float w, float s) {
    float t = fminf(fmaxf(w / s, -127.f), 127.f);
    return rintf(t) * s;
}

__device__ __forceinline__ void fill_bn(const float* bn, int c, float* A, float* Bt) {
    for (int i = threadIdx.x; i < c; i += blockDim.x) {
        float g = bn[i], b = bn[c + i], m = bn[2 * c + i], v = bn[3 * c + i];
        float al = g * rsqrtf(v + EPSV);
        A[i] = al;
        Bt[i] = b - m * al;
    }
}

// ---------------------------------------------------------------------------
__global__ void setup_kernel(
    const float* __restrict__ w1,   const float* __restrict__ w2,
    const float* __restrict__ wr1,  const float* __restrict__ wr2,
    const float* __restrict__ wo1a, const float* __restrict__ wo1b, const float* __restrict__ wo1c,
    const float* __restrict__ wo2a, const float* __restrict__ wo2b, const float* __restrict__ wo2c,
    const float* __restrict__ bn1,  const float* __restrict__ bn2,
    const float* __restrict__ bnr1, const float* __restrict__ bnr2,
    const float* __restrict__ bno1a, const float* __restrict__ bno1b, const float* __restrict__ bno1c,
    const float* __restrict__ bno2a, const float* __restrict__ bno2b, const float* __restrict__ bno2c)
{
    const int blk = blockIdx.x, tid = threadIdx.x;
    if (blk < 10) {
        const float* w; int n;
        switch (blk) {
            case 0: w = w1;   n = 65;   break;
            case 1: w = w2;   n = 450;  break;
            case 2: w = wr1;  n = 100;  break;
            case 3: w = wr2;  n = 100;  break;
            case 4: w = wo1a; n = 9800; break;
            case 5: w = wo2a; n = 9800; break;
            case 6: w = wo1b; n = 2100; break;
            case 7: w = wo2b; n = 2100; break;
            case 8: w = wo1c; n = 30;   break;
            default: w = wo2c; n = 30;  break;
        }
        __shared__ float red[256];
        float m = 0.f;
        for (int i = tid; i < n; i += 256) m = fmaxf(m, fabsf(w[i]));
        red[tid] = m;
        __syncthreads();
        for (int s = 128; s > 0; s >>= 1) {
            if (tid < s) red[tid] = fmaxf(red[tid], red[tid + s]);
            __syncthreads();
        }
        const float s = red[0] / 127.f;

        if (blk == 0) {
            for (int j = tid; j < 80; j += 256) {
                int c = j >> 4, k = j & 15;
                g_small[W1OFF + j] = (k < 13) ? quantv(w[c * 13 + k], s) : 0.f;
            }
        } else if (blk == 1) {
            for (int j = tid; j < 600; j += 256) {
                int row = j / 12, k = j - row * 12;
                g_small[W2OFF + j] = (k < 9) ? quantv(w[row * 9 + k], s) : 0.f;
            }
        } else if (blk == 2 || blk == 3) {
            // transposed: dst[ci*16 + 8g + k] = quant(w[(5g+k)*10 + ci]), k<5
            float* dst = g_small + (blk == 2 ? R1TOFF : R2TOFF);
            for (int j = tid; j < 160; j += 256) {
                int ci = j >> 4, rem = j & 15;
                int g = rem >> 3, k = rem & 7;
                int c = 5 * g + k;
                dst[j] = (k < 5) ? quantv(w[c * 10 + ci], s) : 0.f;
            }
        } else if (blk == 4 || blk == 5) {
            float* dst = g_qoa + (blk - 4) * 9800;
            for (int j = tid; j < 9800; j += 256) {
                int i4 = j / 280, rem = j - i4 * 280;
                int c = rem >> 2, t = rem & 3;
                dst[j] = quantv(w[c * 140 + i4 * 4 + t], s);
            }
        } else if (blk == 6 || blk == 7) {
            float* dst = g_qob + (blk - 6) * 2160;
            for (int j = tid; j < 2160; j += 256) {
                int i4 = j / 120, rem = j - i4 * 120;
                int c = rem >> 2, t = rem & 3;
                int i = i4 * 4 + t;
                dst[j] = (i < 70) ? quantv(w[c * 70 + i], s) : 0.f;
            }
        } else {
            float* dst = g_small + QOCOFF + (blk - 8) * 32;
            if (tid < 32) dst[tid] = (tid < 30) ? quantv(w[tid], s) : 0.f;
        }
    } else {
        fill_bn(bn1, 5,  g_small + A1OFF,  g_small + B1OFF);
        fill_bn(bn2, 10, g_small + A2OFF,  g_small + B2OFF);
        fill_bn(bnr1, 10, g_small + AR1OFF, g_small + BR1OFF);
        fill_bn(bnr2, 10, g_small + AR2OFF, g_small + BR2OFF);
        fill_bn(bno1a, 70, g_small + AOAOFF,      g_small + BOAOFF);
        fill_bn(bno2a, 70, g_small + AOAOFF + 70, g_small + BOAOFF + 70);
        fill_bn(bno1b, 30, g_small + AOBOFF,      g_small + BOBOFF);
        fill_bn(bno2b, 30, g_small + AOBOFF + 30, g_small + BOBOFF + 30);
        fill_bn(bno1c, 1, g_small + AOCOFF,     g_small + BOCOFF);
        fill_bn(bno2c, 1, g_small + AOCOFF + 1, g_small + BOCOFF + 1);
    }
}

// ---------------------------------------------------------------------------
// Per-warp workspace (floats). Activations float4 = (e0,e1,e2,e3).
//   X  @0     float4[256] (1024)   [T aliases X; A aliases X]
//   H1 @1024  float4[245] (980)    stride-49 rows  [F aliases H1]
//   H2 @2004  float4[144] (576)    [B aliases H2]
#define XOFF  0
#define H1OFF 1024
#define H2OFF 2004
#define FOFF  1024
#define AOFF  0
#define BOFF  2004
#define WS_N  2580

__device__ __forceinline__ void ld4(float* d, const float* s) {
    float4 v = *(const float4*)s;
    d[0] = v.x; d[1] = v.y; d[2] = v.z; d[3] = v.w;
}

// acc[e] += |u[e] - w| ; diff as FFMA-imm (multiplier = -1.0 immediate, rt 1)
__device__ __forceinline__ void acc4(float4& a, float4 u, float w) {
    a.x += fabsf(fmaf(w, -1.0f, u.x));
    a.y += fabsf(fmaf(w, -1.0f, u.y));
    a.z += fabsf(fmaf(w, -1.0f, u.z));
    a.w += fabsf(fmaf(w, -1.0f, u.w));
}

__device__ __forceinline__ float4 add4(float4 a, float4 b) {
    return make_float4(a.x + b.x, a.y + b.y, a.z + b.z, a.w + b.w);
}

__device__ __forceinline__ float4 bnrelu4(float4 a, float al, float be) {
    return make_float4(fmaxf(fmaf(-a.x, al, be), 0.f),
                       fmaxf(fmaf(-a.y, al, be), 0.f),
                       fmaxf(fmaf(-a.z, al, be), 0.f),
                       fmaxf(fmaf(-a.w, al, be), 0.f));
}

#define ZERO4 make_float4(0.f, 0.f, 0.f, 0.f)

__global__ void __launch_bounds__(128) taunet_main(const float* __restrict__ x,
                                                   float* __restrict__ out, int nB)
{
    __shared__ __align__(16) float s_small[SMALL_N];
    __shared__ __align__(16) float s_ws[4][WS_N];

    for (int i = threadIdx.x; i < SMALL_N; i += 128) s_small[i] = g_small[i];
    __syncthreads();

    const int warp = threadIdx.x >> 5, lane = threadIdx.x & 31;
    float* ws = s_ws[warp];
    float4* X4  = (float4*)(ws + XOFF);
    float4* H14 = (float4*)(ws + H1OFF);
    float4* H24 = (float4*)(ws + H2OFF);
    float4* T4  = (float4*)(ws + XOFF);
    float4* F4  = (float4*)(ws + FOFF);
    float4* A4  = (float4*)(ws + AOFF);
    float4* B4  = (float4*)(ws + BOFF);

    // ---- per-lane o-layer slot precompute ----
    const int j2 = lane + 64, j3 = lane + 96;
    const int j4 = (lane + 128 < 140) ? lane + 128 : 139;
    const int oa2 = (j2 < 70) ? j2 : (2450 + (j2 - 70));
    const int oa3 = 2450 + (j3 - 70);
    const int oa4 = 2450 + (j4 - 70);
    const int d2 = (j2 < 70) ? j2 : (72 + (j2 - 70));
    const int d3 = 72 + (j3 - 70);
    const int d4 = 72 + (j4 - 70);
    const int jb1 = (lane + 32 < 60) ? lane + 32 : 59;
    const int obb0 = lane / 30, obc0 = lane - 30 * obb0;
    const int ob0 = obb0 * 540 + obc0;
    const int ob1 = 540 + (jb1 - 30);
    // r1/r2 mapping: lanes 0..27 -> (p, g)
    const int rp = lane >> 1, rg = lane & 1;

    const int nQ = (nB + 3) >> 2;
    const int gw = blockIdx.x * 4 + warp;
    const int stride = gridDim.x * 4;

    for (int q = gw; q < nQ; q += stride) {
        const int e0 = 4 * q;
        const int e1 = (e0 + 1 < nB) ? e0 + 1 : nB - 1;
        const int e2 = (e0 + 2 < nB) ? e0 + 2 : nB - 1;
        const int e3 = (e0 + 3 < nB) ? e0 + 3 : nB - 1;

        // ---- stage 4 input rows, transposed into float4-per-position ----
        {
            const float4* r0 = (const float4*)(x + (size_t)e0 * 256);
            const float4* r1 = (const float4*)(x + (size_t)e1 * 256);
            const float4* r2 = (const float4*)(x + (size_t)e2 * 256);
            const float4* r3 = (const float4*)(x + (size_t)e3 * 256);
            #pragma unroll
            for (int i = 0; i < 2; i++) {
                int m = lane + 32 * i;
                float4 a = __ldg(r0 + m);
                float4 b = __ldg(r1 + m);
                float4 c = __ldg(r2 + m);
                float4 d = __ldg(r3 + m);
                X4[4 * m + 0] = make_float4(a.x, b.x, c.x, d.x);
                X4[4 * m + 1] = make_float4(a.y, b.y, c.y, d.y);
                X4[4 * m + 2] = make_float4(a.z, b.z, c.z, d.z);
                X4[4 * m + 3] = make_float4(a.w, b.w, c.w, d.w);
            }
        }
        __syncwarp();

        // ---- pre1: 125 dual-position tasks (5ch x 25pd), K=13, stride 5 ----
        #pragma unroll 1
        for (int r = 0; r < 4; r++) {
            int idx = lane + 32 * r;
            if (idx < 125) {
                int c = idx / 25, pd = idx - 25 * c;
                int p0 = 2 * pd;
                bool dual = (pd < 24);
                float w[16];
                const float* wb = s_small + W1OFF + c * 16;
                ld4(w, wb); ld4(w + 4, wb + 4); ld4(w + 8, wb + 8); ld4(w + 12, wb + 12);
                const float4* xp = X4 + 5 * p0;
                float4 A0 = ZERO4, B0 = ZERO4, A1 = ZERO4, B1 = ZERO4;
                #pragma unroll
                for (int k = 0; k < 13; k++) {
                    float4 a = xp[k];
                    if (k & 1) acc4(B0, a, w[k]); else acc4(A0, a, w[k]);
                    if (k >= 5) {
                        if ((k - 5) & 1) acc4(B1, a, w[k - 5]); else acc4(A1, a, w[k - 5]);
                    }
                }
                if (dual) {
                    #pragma unroll
                    for (int k = 13; k < 18; k++) {
                        float4 a = xp[k];
                        if ((k - 5) & 1) acc4(B1, a, w[k - 5]); else acc4(A1, a, w[k - 5]);
                    }
                }
                float al = s_small[A1OFF + c], be = s_small[B1OFF + c];
                H14[c * 49 + p0] = bnrelu4(add4(A0, B0), al, be);
                if (dual)
                    H14[c * 49 + p0 + 1] = bnrelu4(add4(A1, B1), al, be);
            }
        }
        __syncwarp();

        // ---- pre2: 140 tasks (10ch x 14pos), 5cin x K=9, stride 3 ----
        #pragma unroll 1
        for (int r = 0; r < 5; r++) {
            int idx = lane + 32 * r;
            if (idx < 140) {
                int c = idx / 14, p = idx - 14 * c;
                const float4* hp = H14 + 3 * p;
                float4 Aa = ZERO4, Bb = ZERO4;
                #pragma unroll
                for (int ci = 0; ci < 5; ci++) {
                    float w[12];
                    const float* wb = s_small + W2OFF + (c * 5 + ci) * 12;
                    ld4(w, wb); ld4(w + 4, wb + 4); ld4(w + 8, wb + 8);
                    const float4* hc = hp + ci * 49;
                    #pragma unroll
                    for (int k = 0; k < 9; k++) {
                        if (k & 1) acc4(Bb, hc[k], w[k]); else acc4(Aa, hc[k], w[k]);
                    }
                }
                H24[c * 14 + p] = bnrelu4(add4(Aa, Bb), s_small[A2OFF + c], s_small[B2OFF + c]);
            }
        }
        __syncwarp();

        // ---- r1: position-major, lanes 0..27 = (p, g); 5 channels each ----
        if (lane < 28) {
            float4 acc[5];
            #pragma unroll
            for (int j = 0; j < 5; j++) acc[j] = ZERO4;
            const float* wt = s_small + R1TOFF + 8 * rg;
            #pragma unroll
            for (int ci = 0; ci < 10; ci++) {
                float4 a = H24[ci * 14 + rp];
                float w8[8];
                ld4(w8, wt + ci * 16); ld4(w8 + 4, wt + ci * 16 + 4);
                #pragma unroll
                for (int j = 0; j < 5; j++) acc4(acc[j], a, w8[j]);
            }
            #pragma unroll
            for (int j = 0; j < 5; j++) {
                int c = 5 * rg + j;
                T4[c * 14 + rp] = bnrelu4(acc[j], s_small[AR1OFF + c], s_small[BR1OFF + c]);
            }
        }
        __syncwarp();

        // ---- r2 + residual: same mapping, F over dead H1 ----
        if (lane < 28) {
            float4 acc[5];
            #pragma unroll
            for (int j = 0; j < 5; j++) acc[j] = ZERO4;
            const float* wt = s_small + R2TOFF + 8 * rg;
            #pragma unroll
            for (int ci = 0; ci < 10; ci++) {
                float4 a = T4[ci * 14 + rp];
                float w8[8];
                ld4(w8, wt + ci * 16); ld4(w8 + 4, wt + ci * 16 + 4);
                #pragma unroll
                for (int j = 0; j < 5; j++) acc4(acc[j], a, w8[j]);
            }
            #pragma unroll
            for (int j = 0; j < 5; j++) {
                int c = 5 * rg + j;
                float al = s_small[AR2OFF + c], be = s_small[BR2OFF + c];
                float4 h2v = H24[c * 14 + rp];
                float4 a = acc[j];
                F4[c * 14 + rp] = make_float4(
                    fmaxf(fmaf(-a.x, al, be) + h2v.x, 0.f),
                    fmaxf(fmaf(-a.y, al, be) + h2v.y, 0.f),
                    fmaxf(fmaf(-a.z, al, be) + h2v.z, 0.f),
                    fmaxf(fmaf(-a.w, al, be) + h2v.w, 0.f));
            }
        }
        if (lane < 4) F4[140 + lane] = ZERO4;
        __syncwarp();

        // ---- oa: 5 channel slots x 4 packed elements ----
        {
            float4 acc[5];
            #pragma unroll
            for (int s = 0; s < 5; s++) acc[s] = ZERO4;

            const int slots[5] = {lane, lane + 32, oa2, oa3, oa4};
            const float4* QA = (const float4*)g_qoa;

            #pragma unroll 5
            for (int i4 = 0; i4 < 35; i4++) {
                float4 u0 = F4[4 * i4 + 0];
                float4 u1 = F4[4 * i4 + 1];
                float4 u2 = F4[4 * i4 + 2];
                float4 u3 = F4[4 * i4 + 3];
                const float4* qrow = QA + i4 * 70;
                #pragma unroll
                for (int s = 0; s < 5; s++) {
                    float4 w = __ldg(qrow + slots[s]);
                    acc4(acc[s], u0, w.x);
                    acc4(acc[s], u1, w.y);
                    acc4(acc[s], u2, w.z);
                    acc4(acc[s], u3, w.w);
                }
            }
            __syncwarp();   // F reads done before A overwrite of X region

            const int js[5] = {lane, lane + 32, j2, j3, j4};
            const int ds[5] = {lane, lane + 32, d2, d3, d4};
            #pragma unroll
            for (int s = 0; s < 5; s++) {
                A4[ds[s]] = bnrelu4(acc[s], s_small[AOAOFF + js[s]], s_small[BOAOFF + js[s]]);
            }
            if (lane < 2) {
                A4[70 + lane]  = ZERO4;
                A4[142 + lane] = ZERO4;
            }
        }
        __syncwarp();

        // ---- ob: 2 channel slots x 4 packed elements ----
        {
            float4 b0 = ZERO4;
            float4 b1 = ZERO4;
            const float4* QB = (const float4*)g_qob;
            const float4* a0p = A4 + obb0 * 72;
            const float4* a1p = A4 + 72;

            #pragma unroll 6
            for (int i4 = 0; i4 < 18; i4++) {
                float4 w0 = __ldg(QB + i4 * 30 + ob0);
                acc4(b0, a0p[4 * i4 + 0], w0.x);
                acc4(b0, a0p[4 * i4 + 1], w0.y);
                acc4(b0, a0p[4 * i4 + 2], w0.z);
                acc4(b0, a0p[4 * i4 + 3], w0.w);
                float4 w1 = __ldg(QB + i4 * 30 + ob1);
                acc4(b1, a1p[4 * i4 + 0], w1.x);
                acc4(b1, a1p[4 * i4 + 1], w1.y);
                acc4(b1, a1p[4 * i4 + 2], w1.z);
                acc4(b1, a1p[4 * i4 + 3], w1.w);
            }
            __syncwarp();   // A reads done before B overwrite of H2 region

            B4[obb0 * 32 + obc0] = bnrelu4(b0, s_small[AOBOFF + lane], s_small[BOBOFF + lane]);
            B4[32 + (jb1 - 30)]  = bnrelu4(b1, s_small[AOBOFF + jb1], s_small[BOBOFF + jb1]);
            if (lane < 2) {
                B4[30 + lane] = ZERO4;
                B4[62 + lane] = ZERO4;
            }
        }
        __syncwarp();

        // ---- oc: 8 reductions (4 elems x 2 branches) ----
        {
            float w0 = s_small[QOCOFF + lane], w1 = s_small[QOCOFF + 32 + lane];
            float4 p0 = B4[lane];        // amp branch, 4 elems
            float4 p1 = B4[32 + lane];   // inten branch
            float vA0 = fabsf(p0.x - w0), vA1 = fabsf(p0.y - w0);
            float vA2 = fabsf(p0.z - w0), vA3 = fabsf(p0.w - w0);
            float vI0 = fabsf(p1.x - w1), vI1 = fabsf(p1.y - w1);
            float vI2 = fabsf(p1.z - w1), vI3 = fabsf(p1.w - w1);
            #pragma unroll
            for (int s = 16; s > 0; s >>= 1) {
                vA0 += __shfl_xor_sync(0xffffffffu, vA0, s);
                vA1 += __shfl_xor_sync(0xffffffffu, vA1, s);
                vA2 += __shfl_xor_sync(0xffffffffu, vA2, s);
                vA3 += __shfl_xor_sync(0xffffffffu, vA3, s);
                vI0 += __shfl_xor_sync(0xffffffffu, vI0, s);
                vI1 += __shfl_xor_sync(0xffffffffu, vI1, s);
                vI2 += __shfl_xor_sync(0xffffffffu, vI2, s);
                vI3 += __shfl_xor_sync(0xffffffffu, vI3, s);
            }
            if (lane == 0) {
                float aA = s_small[AOCOFF],     bA = s_small[BOCOFF];
                float aI = s_small[AOCOFF + 1], bI = s_small[BOCOFF + 1];
                float vA[4] = {vA0, vA1, vA2, vA3};
                float vI[4] = {vI0, vI1, vI2, vI3};
                #pragma unroll
                for (int i = 0; i < 4; i++) {
                    if (e0 + i < nB) {
                        out[e0 + i]      = fmaxf(fmaf(-vA[i], aA, bA), 0.f);
                        out[nB + e0 + i] = fmaxf(fmaf(-vI[i], aI, bI), 0.f);
                    }
                }
            }
        }
        __syncwarp();   // B reads done before next iteration overwrites
    }
}

// ---------------------------------------------------------------------------
extern "C" void kernel_launch(void* const* d_in, const int* in_sizes, int n_in,
                              void* d_out, int out_size)
{
    const float* x     = (const float*)d_in[0];
    const float* w1    = (const float*)d_in[1];
    const float* bn1   = (const float*)d_in[2];
    const float* w2    = (const float*)d_in[3];
    const float* bn2   = (const float*)d_in[4];
    const float* wr1   = (const float*)d_in[5];
    const float* bnr1  = (const float*)d_in[6];
    const float* wr2   = (const float*)d_in[7];
    const float* bnr2  = (const float*)d_in[8];
    const float* wo1a  = (const float*)d_in[9];
    const float* bno1a = (const float*)d_in[10];
    const float* wo1b  = (const float*)d_in[11];
    const float* bno1b = (const float*)d_in[12];
    const float* wo1c  = (const float*)d_in[13];
    const float* bno1c = (const float*)d_in[14];
    const float* wo2a  = (const float*)d_in[15];
    const float* bno2a = (const float*)d_in[16];
    const float* wo2b  = (const float*)d_in[17];
    const float* bno2b = (const float*)d_in[18];
    const float* wo2c  = (const float*)d_in[19];
    const float* bno2c = (const float*)d_in[20];

    const int nB = in_sizes[0] / 256;

    setup_kernel<<<11, 256>>>(w1, w2, wr1, wr2, wo1a, wo1b, wo1c, wo2a, wo2b, wo2c,
                              bn1, bn2, bnr1, bnr2, bno1a, bno1b, bno1c,
                              bno2a, bno2b, bno2c);
    taunet_main<<<512, 128>>>(x, (float*)d_out, nB);
}

// round 9
// speedup vs baseline: 1.1634x; 1.0390x over previous
#include <cuda_runtime.h>

// ============================================================================
// AdderNet TauNet R9: R8 + FORCED FFMA-imm diff via inline PTX
//                     (fma.rn.f32 d, w, -1.0imm, u  -> SASS 0x823, rt_SMSP=1).
// ============================================================================

#define EPSV 1e-5f

// ---- s_small layout (floats), compact ----
#define W1OFF   0      // 5 x 16
#define W2OFF   80     // 50 x 12
#define R1TOFF  680    // 10ci x 16  (transposed: [ci][8g + j] = w[5g+j][ci])
#define R2TOFF  840    // 10ci x 16
#define A1OFF   1000
#define B1OFF   1005
#define A2OFF   1010
#define B2OFF   1020
#define AR1OFF  1030
#define BR1OFF  1040
#define AR2OFF  1050
#define BR2OFF  1060
#define AOAOFF  1070   // 140
#define BOAOFF  1210   // 140
#define AOBOFF  1350   // 60
#define BOBOFF  1410   // 60
#define AOCOFF  1470   // 2
#define BOCOFF  1472   // 2
#define QOCOFF  1474   // 64
#define SMALL_N 1540

__device__ float g_small[1544];
__device__ float g_qoa[2 * 35 * 70 * 4];   // [branch][i/4][c][4]
__device__ float g_qob[2 * 18 * 30 * 4];

__device__ __forceinline__ float quantv(float w, float s) {
    float t = fminf(fmaxf(w / s, -127.f), 127.f);
    return rintf(t) * s;
}

__device__ __forceinline__ void fill_bn(const float* bn, int c, float* A, float* Bt) {
    for (int i = threadIdx.x; i < c; i += blockDim.x) {
        float g = bn[i], b = bn[c + i], m = bn[2 * c + i], v = bn[3 * c + i];
        float al = g * rsqrtf(v + EPSV);
        A[i] = al;
        Bt[i] = b - m * al;
    }
}

// ---------------------------------------------------------------------------
__global__ void setup_kernel(
    const float* __restrict__ w1,   const float* __restrict__ w2,
    const float* __restrict__ wr1,  const float* __restrict__ wr2,
    const float* __restrict__ wo1a, const float* __restrict__ wo1b, const float* __restrict__ wo1c,
    const float* __restrict__ wo2a, const float* __restrict__ wo2b, const float* __restrict__ wo2c,
    const float* __restrict__ bn1,  const float* __restrict__ bn2,
    const float* __restrict__ bnr1, const float* __restrict__ bnr2,
    const float* __restrict__ bno1a, const float* __restrict__ bno1b, const float* __restrict__ bno1c,
    const float* __restrict__ bno2a, const float* __restrict__ bno2b, const float* __restrict__ bno2c)
{
    const int blk = blockIdx.x, tid = threadIdx.x;
    if (blk < 10) {
        const float* w; int n;
        switch (blk) {
            case 0: w = w1;   n = 65;   break;
            case 1: w = w2;   n = 450;  break;
            case 2: w = wr1;  n = 100;  break;
            case 3: w = wr2;  n = 100;  break;
            case 4: w = wo1a; n = 9800; break;
            case 5: w = wo2a; n = 9800; break;
            case 6: w = wo1b; n = 2100; break;
            case 7: w = wo2b; n = 2100; break;
            case 8: w = wo1c; n = 30;   break;
            default: w = wo2c; n = 30;  break;
        }
        __shared__ float red[256];
        float m = 0.f;
        for (int i = tid; i < n; i += 256) m = fmaxf(m, fabsf(w[i]));
        red[tid] = m;
        __syncthreads();
        for (int s = 128; s > 0; s >>= 1) {
            if (tid < s) red[tid] = fmaxf(red[tid], red[tid + s]);
            __syncthreads();
        }
        const float s = red[0] / 127.f;

        if (blk == 0) {
            for (int j = tid; j < 80; j += 256) {
                int c = j >> 4, k = j & 15;
                g_small[W1OFF + j] = (k < 13) ? quantv(w[c * 13 + k], s) : 0.f;
            }
        } else if (blk == 1) {
            for (int j = tid; j < 600; j += 256) {
                int row = j / 12, k = j - row * 12;
                g_small[W2OFF + j] = (k < 9) ? quantv(w[row * 9 + k], s) : 0.f;
            }
        } else if (blk == 2 || blk == 3) {
            // transposed: dst[ci*16 + 8g + k] = quant(w[(5g+k)*10 + ci]), k<5
            float* dst = g_small + (blk == 2 ? R1TOFF : R2TOFF);
            for (int j = tid; j < 160; j += 256) {
                int ci = j >> 4, rem = j & 15;
                int g = rem >> 3, k = rem & 7;
                int c = 5 * g + k;
                dst[j] = (k < 5) ? quantv(w[c * 10 + ci], s) : 0.f;
            }
        } else if (blk == 4 || blk == 5) {
            float* dst = g_qoa + (blk - 4) * 9800;
            for (int j = tid; j < 9800; j += 256) {
                int i4 = j / 280, rem = j - i4 * 280;
                int c = rem >> 2, t = rem & 3;
                dst[j] = quantv(w[c * 140 + i4 * 4 + t], s);
            }
        } else if (blk == 6 || blk == 7) {
            float* dst = g_qob + (blk - 6) * 2160;
            for (int j = tid; j < 2160; j += 256) {
                int i4 = j / 120, rem = j - i4 * 120;
                int c = rem >> 2, t = rem & 3;
                int i = i4 * 4 + t;
                dst[j] = (i < 70) ? quantv(w[c * 70 + i], s) : 0.f;
            }
        } else {
            float* dst = g_small + QOCOFF + (blk - 8) * 32;
            if (tid < 32) dst[tid] = (tid < 30) ? quantv(w[tid], s) : 0.f;
        }
    } else {
        fill_bn(bn1, 5,  g_small + A1OFF,  g_small + B1OFF);
        fill_bn(bn2, 10, g_small + A2OFF,  g_small + B2OFF);
        fill_bn(bnr1, 10, g_small + AR1OFF, g_small + BR1OFF);
        fill_bn(bnr2, 10, g_small + AR2OFF, g_small + BR2OFF);
        fill_bn(bno1a, 70, g_small + AOAOFF,      g_small + BOAOFF);
        fill_bn(bno2a, 70, g_small + AOAOFF + 70, g_small + BOAOFF + 70);
        fill_bn(bno1b, 30, g_small + AOBOFF,      g_small + BOBOFF);
        fill_bn(bno2b, 30, g_small + AOBOFF + 30, g_small + BOBOFF + 30);
        fill_bn(bno1c, 1, g_small + AOCOFF,     g_small + BOCOFF);
        fill_bn(bno2c, 1, g_small + AOCOFF + 1, g_small + BOCOFF + 1);
    }
}

// ---------------------------------------------------------------------------
// Per-warp workspace (floats). Activations float4 = (e0,e1,e2,e3).
//   X  @0     float4[256] (1024)   [T aliases X; A aliases X]
//   H1 @1024  float4[245] (980)    stride-49 rows  [F aliases H1]
//   H2 @2004  float4[144] (576)    [B aliases H2]
#define XOFF  0
#define H1OFF 1024
#define H2OFF 2004
#define FOFF  1024
#define AOFF  0
#define BOFF  2004
#define WS_N  2580

__device__ __forceinline__ void ld4(float* d, const float* s) {
    float4 v = *(const float4*)s;
    d[0] = v.x; d[1] = v.y; d[2] = v.z; d[3] = v.w;
}

// d = u - w, FORCED as FFMA with src1 immediate -1.0 (SASS 0x823 form, rt 1).
// fma(w, -1, u) is bit-identical to u - w (the product is exact).
__device__ __forceinline__ float fdiff(float u, float w) {
    float d;
    asm("fma.rn.f32 %0, %1, 0fBF800000, %2;" : "=f"(d) : "f"(w), "f"(u));
    return d;
}

// acc[e] += |u[e] - w|  (FFMA-imm diff + FADD-with-|src| accumulate)
__device__ __forceinline__ void acc4(float4& a, float4 u, float w) {
    a.x += fabsf(fdiff(u.x, w));
    a.y += fabsf(fdiff(u.y, w));
    a.z += fabsf(fdiff(u.z, w));
    a.w += fabsf(fdiff(u.w, w));
}

__device__ __forceinline__ float4 add4(float4 a, float4 b) {
    return make_float4(a.x + b.x, a.y + b.y, a.z + b.z, a.w + b.w);
}

__device__ __forceinline__ float4 bnrelu4(float4 a, float al, float be) {
    return make_float4(fmaxf(fmaf(-a.x, al, be), 0.f),
                       fmaxf(fmaf(-a.y, al, be), 0.f),
                       fmaxf(fmaf(-a.z, al, be), 0.f),
                       fmaxf(fmaf(-a.w, al, be), 0.f));
}

#define ZERO4 make_float4(0.f, 0.f, 0.f, 0.f)

__global__ void __launch_bounds__(128) taunet_main(const float* __restrict__ x,
                                                   float* __restrict__ out, int nB)
{
    __shared__ __align__(16) float s_small[SMALL_N];
    __shared__ __align__(16) float s_ws[4][WS_N];

    for (int i = threadIdx.x; i < SMALL_N; i += 128) s_small[i] = g_small[i];
    __syncthreads();

    const int warp = threadIdx.x >> 5, lane = threadIdx.x & 31;
    float* ws = s_ws[warp];
    float4* X4  = (float4*)(ws + XOFF);
    float4* H14 = (float4*)(ws + H1OFF);
    float4* H24 = (float4*)(ws + H2OFF);
    float4* T4  = (float4*)(ws + XOFF);
    float4* F4  = (float4*)(ws + FOFF);
    float4* A4  = (float4*)(ws + AOFF);
    float4* B4  = (float4*)(ws + BOFF);

    // ---- per-lane o-layer slot precompute ----
    const int j2 = lane + 64, j3 = lane + 96;
    const int j4 = (lane + 128 < 140) ? lane + 128 : 139;
    const int oa2 = (j2 < 70) ? j2 : (2450 + (j2 - 70));
    const int oa3 = 2450 + (j3 - 70);
    const int oa4 = 2450 + (j4 - 70);
    const int d2 = (j2 < 70) ? j2 : (72 + (j2 - 70));
    const int d3 = 72 + (j3 - 70);
    const int d4 = 72 + (j4 - 70);
    const int jb1 = (lane + 32 < 60) ? lane + 32 : 59;
    const int obb0 = lane / 30, obc0 = lane - 30 * obb0;
    const int ob0 = obb0 * 540 + obc0;
    const int ob1 = 540 + (jb1 - 30);
    // r1/r2 mapping: lanes 0..27 -> (p, g)
    const int rp = lane >> 1, rg = lane & 1;

    const int nQ = (nB + 3) >> 2;
    const int gw = blockIdx.x * 4 + warp;
    const int stride = gridDim.x * 4;

    for (int q = gw; q < nQ; q += stride) {
        const int e0 = 4 * q;
        const int e1 = (e0 + 1 < nB) ? e0 + 1 : nB - 1;
        const int e2 = (e0 + 2 < nB) ? e0 + 2 : nB - 1;
        const int e3 = (e0 + 3 < nB) ? e0 + 3 : nB - 1;

        // ---- stage 4 input rows, transposed into float4-per-position ----
        {
            const float4* r0 = (const float4*)(x + (size_t)e0 * 256);
            const float4* r1 = (const float4*)(x + (size_t)e1 * 256);
            const float4* r2 = (const float4*)(x + (size_t)e2 * 256);
            const float4* r3 = (const float4*)(x + (size_t)e3 * 256);
            #pragma unroll
            for (int i = 0; i < 2; i++) {
                int m = lane + 32 * i;
                float4 a = __ldg(r0 + m);
                float4 b = __ldg(r1 + m);
                float4 c = __ldg(r2 + m);
                float4 d = __ldg(r3 + m);
                X4[4 * m + 0] = make_float4(a.x, b.x, c.x, d.x);
                X4[4 * m + 1] = make_float4(a.y, b.y, c.y, d.y);
                X4[4 * m + 2] = make_float4(a.z, b.z, c.z, d.z);
                X4[4 * m + 3] = make_float4(a.w, b.w, c.w, d.w);
            }
        }
        __syncwarp();

        // ---- pre1: 125 dual-position tasks (5ch x 25pd), K=13, stride 5 ----
        #pragma unroll 1
        for (int r = 0; r < 4; r++) {
            int idx = lane + 32 * r;
            if (idx < 125) {
                int c = idx / 25, pd = idx - 25 * c;
                int p0 = 2 * pd;
                bool dual = (pd < 24);
                float w[16];
                const float* wb = s_small + W1OFF + c * 16;
                ld4(w, wb); ld4(w + 4, wb + 4); ld4(w + 8, wb + 8); ld4(w + 12, wb + 12);
                const float4* xp = X4 + 5 * p0;
                float4 A0 = ZERO4, B0 = ZERO4, A1 = ZERO4, B1 = ZERO4;
                #pragma unroll
                for (int k = 0; k < 13; k++) {
                    float4 a = xp[k];
                    if (k & 1) acc4(B0, a, w[k]); else acc4(A0, a, w[k]);
                    if (k >= 5) {
                        if ((k - 5) & 1) acc4(B1, a, w[k - 5]); else acc4(A1, a, w[k - 5]);
                    }
                }
                if (dual) {
                    #pragma unroll
                    for (int k = 13; k < 18; k++) {
                        float4 a = xp[k];
                        if ((k - 5) & 1) acc4(B1, a, w[k - 5]); else acc4(A1, a, w[k - 5]);
                    }
                }
                float al = s_small[A1OFF + c], be = s_small[B1OFF + c];
                H14[c * 49 + p0] = bnrelu4(add4(A0, B0), al, be);
                if (dual)
                    H14[c * 49 + p0 + 1] = bnrelu4(add4(A1, B1), al, be);
            }
        }
        __syncwarp();

        // ---- pre2: 140 tasks (10ch x 14pos), 5cin x K=9, stride 3 ----
        #pragma unroll 1
        for (int r = 0; r < 5; r++) {
            int idx = lane + 32 * r;
            if (idx < 140) {
                int c = idx / 14, p = idx - 14 * c;
                const float4* hp = H14 + 3 * p;
                float4 Aa = ZERO4, Bb = ZERO4;
                #pragma unroll
                for (int ci = 0; ci < 5; ci++) {
                    float w[12];
                    const float* wb = s_small + W2OFF + (c * 5 + ci) * 12;
                    ld4(w, wb); ld4(w + 4, wb + 4); ld4(w + 8, wb + 8);
                    const float4* hc = hp + ci * 49;
                    #pragma unroll
                    for (int k = 0; k < 9; k++) {
                        if (k & 1) acc4(Bb, hc[k], w[k]); else acc4(Aa, hc[k], w[k]);
                    }
                }
                H24[c * 14 + p] = bnrelu4(add4(Aa, Bb), s_small[A2OFF + c], s_small[B2OFF + c]);
            }
        }
        __syncwarp();

        // ---- r1: position-major, lanes 0..27 = (p, g); 5 channels each ----
        if (lane < 28) {
            float4 acc[5];
            #pragma unroll
            for (int j = 0; j < 5; j++) acc[j] = ZERO4;
            const float* wt = s_small + R1TOFF + 8 * rg;
            #pragma unroll
            for (int ci = 0; ci < 10; ci++) {
                float4 a = H24[ci * 14 + rp];
                float w8[8];
                ld4(w8, wt + ci * 16); ld4(w8 + 4, wt + ci * 16 + 4);
                #pragma unroll
                for (int j = 0; j < 5; j++) acc4(acc[j], a, w8[j]);
            }
            #pragma unroll
            for (int j = 0; j < 5; j++) {
                int c = 5 * rg + j;
                T4[c * 14 + rp] = bnrelu4(acc[j], s_small[AR1OFF + c], s_small[BR1OFF + c]);
            }
        }
        __syncwarp();

        // ---- r2 + residual: same mapping, F over dead H1 ----
        if (lane < 28) {
            float4 acc[5];
            #pragma unroll
            for (int j = 0; j < 5; j++) acc[j] = ZERO4;
            const float* wt = s_small + R2TOFF + 8 * rg;
            #pragma unroll
            for (int ci = 0; ci < 10; ci++) {
                float4 a = T4[ci * 14 + rp];
                float w8[8];
                ld4(w8, wt + ci * 16); ld4(w8 + 4, wt + ci * 16 + 4);
                #pragma unroll
                for (int j = 0; j < 5; j++) acc4(acc[j], a, w8[j]);
            }
            #pragma unroll
            for (int j = 0; j < 5; j++) {
                int c = 5 * rg + j;
                float al = s_small[AR2OFF + c], be = s_small[BR2OFF + c];
                float4 h2v = H24[c * 14 + rp];
                float4 a = acc[j];
                F4[c * 14 + rp] = make_float4(
                    fmaxf(fmaf(-a.x, al, be) + h2v.x, 0.f),
                    fmaxf(fmaf(-a.y, al, be) + h2v.y, 0.f),
                    fmaxf(fmaf(-a.z, al, be) + h2v.z, 0.f),
                    fmaxf(fmaf(-a.w, al, be) + h2v.w, 0.f));
            }
        }
        if (lane < 4) F4[140 + lane] = ZERO4;
        __syncwarp();

        // ---- oa: 5 channel slots x 4 packed elements ----
        {
            float4 acc[5];
            #pragma unroll
            for (int s = 0; s < 5; s++) acc[s] = ZERO4;

            const int slots[5] = {lane, lane + 32, oa2, oa3, oa4};
            const float4* QA = (const float4*)g_qoa;

            #pragma unroll 5
            for (int i4 = 0; i4 < 35; i4++) {
                float4 u0 = F4[4 * i4 + 0];
                float4 u1 = F4[4 * i4 + 1];
                float4 u2 = F4[4 * i4 + 2];
                float4 u3 = F4[4 * i4 + 3];
                const float4* qrow = QA + i4 * 70;
                #pragma unroll
                for (int s = 0; s < 5; s++) {
                    float4 w = __ldg(qrow + slots[s]);
                    acc4(acc[s], u0, w.x);
                    acc4(acc[s], u1, w.y);
                    acc4(acc[s], u2, w.z);
                    acc4(acc[s], u3, w.w);
                }
            }
            __syncwarp();   // F reads done before A overwrite of X region

            const int js[5] = {lane, lane + 32, j2, j3, j4};
            const int ds[5] = {lane, lane + 32, d2, d3, d4};
            #pragma unroll
            for (int s = 0; s < 5; s++) {
                A4[ds[s]] = bnrelu4(acc[s], s_small[AOAOFF + js[s]], s_small[BOAOFF + js[s]]);
            }
            if (lane < 2) {
                A4[70 + lane]  = ZERO4;
                A4[142 + lane] = ZERO4;
            }
        }
        __syncwarp();

        // ---- ob: 2 channel slots x 4 packed elements ----
        {
            float4 b0 = ZERO4;
            float4 b1 = ZERO4;
            const float4* QB = (const float4*)g_qob;
            const float4* a0p = A4 + obb0 * 72;
            const float4* a1p = A4 + 72;

            #pragma unroll 6
            for (int i4 = 0; i4 < 18; i4++) {
                float4 w0 = __ldg(QB + i4 * 30 + ob0);
                acc4(b0, a0p[4 * i4 + 0], w0.x);
                acc4(b0, a0p[4 * i4 + 1], w0.y);
                acc4(b0, a0p[4 * i4 + 2], w0.z);
                acc4(b0, a0p[4 * i4 + 3], w0.w);
                float4 w1 = __ldg(QB + i4 * 30 + ob1);
                acc4(b1, a1p[4 * i4 + 0], w1.x);
                acc4(b1, a1p[4 * i4 + 1], w1.y);
                acc4(b1, a1p[4 * i4 + 2], w1.z);
                acc4(b1, a1p[4 * i4 + 3], w1.w);
            }
            __syncwarp();   // A reads done before B overwrite of H2 region

            B4[obb0 * 32 + obc0] = bnrelu4(b0, s_small[AOBOFF + lane], s_small[BOBOFF + lane]);
            B4[32 + (jb1 - 30)]  = bnrelu4(b1, s_small[AOBOFF + jb1], s_small[BOBOFF + jb1]);
            if (lane < 2) {
                B4[30 + lane] = ZERO4;
                B4[62 + lane] = ZERO4;
            }
        }
        __syncwarp();

        // ---- oc: 8 reductions (4 elems x 2 branches) ----
        {
            float w0 = s_small[QOCOFF + lane], w1 = s_small[QOCOFF + 32 + lane];
            float4 p0 = B4[lane];        // amp branch, 4 elems
            float4 p1 = B4[32 + lane];   // inten branch
            float vA0 = fabsf(fdiff(p0.x, w0)), vA1 = fabsf(fdiff(p0.y, w0));
            float vA2 = fabsf(fdiff(p0.z, w0)), vA3 = fabsf(fdiff(p0.w, w0));
            float vI0 = fabsf(fdiff(p1.x, w1)), vI1 = fabsf(fdiff(p1.y, w1));
            float vI2 = fabsf(fdiff(p1.z, w1)), vI3 = fabsf(fdiff(p1.w, w1));
            #pragma unroll
            for (int s = 16; s > 0; s >>= 1) {
                vA0 += __shfl_xor_sync(0xffffffffu, vA0, s);
                vA1 += __shfl_xor_sync(0xffffffffu, vA1, s);
                vA2 += __shfl_xor_sync(0xffffffffu, vA2, s);
                vA3 += __shfl_xor_sync(0xffffffffu, vA3, s);
                vI0 += __shfl_xor_sync(0xffffffffu, vI0, s);
                vI1 += __shfl_xor_sync(0xffffffffu, vI1, s);
                vI2 += __shfl_xor_sync(0xffffffffu, vI2, s);
                vI3 += __shfl_xor_sync(0xffffffffu, vI3, s);
            }
            if (lane == 0) {
                float aA = s_small[AOCOFF],     bA = s_small[BOCOFF];
                float aI = s_small[AOCOFF + 1], bI = s_small[BOCOFF + 1];
                float vA[4] = {vA0, vA1, vA2, vA3};
                float vI[4] = {vI0, vI1, vI2, vI3};
                #pragma unroll
                for (int i = 0; i < 4; i++) {
                    if (e0 + i < nB) {
                        out[e0 + i]      = fmaxf(fmaf(-vA[i], aA, bA), 0.f);
                        out[nB + e0 + i] = fmaxf(fmaf(-vI[i], aI, bI), 0.f);
                    }
                }
            }
        }
        __syncwarp();   // B reads done before next iteration overwrites
    }
}

// ---------------------------------------------------------------------------
extern "C" void kernel_launch(void* const* d_in, const int* in_sizes, int n_in,
                              void* d_out, int out_size)
{
    const float* x     = (const float*)d_in[0];
    const float* w1    = (const float*)d_in[1];
    const float* bn1   = (const float*)d_in[2];
    const float* w2    = (const float*)d_in[3];
    const float* bn2   = (const float*)d_in[4];
    const float* wr1   = (const float*)d_in[5];
    const float* bnr1  = (const float*)d_in[6];
    const float* wr2   = (const float*)d_in[7];
    const float* bnr2  = (const float*)d_in[8];
    const float* wo1a  = (const float*)d_in[9];
    const float* bno1a = (const float*)d_in[10];
    const float* wo1b  = (const float*)d_in[11];
    const float* bno1b = (const float*)d_in[12];
    const float* wo1c  = (const float*)d_in[13];
    const float* bno1c = (const float*)d_in[14];
    const float* wo2a  = (const float*)d_in[15];
    const float* bno2a = (const float*)d_in[16];
    const float* wo2b  = (const float*)d_in[17];
    const float* bno2b = (const float*)d_in[18];
    const float* wo2c  = (const float*)d_in[19];
    const float* bno2c = (const float*)d_in[20];

    const int nB = in_sizes[0] / 256;

    setup_kernel<<<11, 256>>>(w1, w2, wr1, wr2, wo1a, wo1b, wo1c, wo2a, wo2b, wo2c,
                              bn1, bn2, bnr1, bnr2, bno1a, bno1b, bno1c,
                              bno2a, bno2b, bno2c);
    taunet_main<<<512, 128>>>(x, (float*)d_out, nB);
}